// round 8
// baseline (speedup 1.0000x reference)
#include <cuda_runtime.h>
#include <cstdint>

// ---------------- problem constants ----------------
#define BATCH 2
#define SEQ   1024
#define DMODEL 768
#define FFDIM 3072
#define NHEAD 12
#define HDIM  64
#define NLAYER 4
#define VOCAB 50257
#define VPAD  50304          // 393*128
#define ROWS (BATCH*SEQ)     // 2048

// ---------------- scratch ----------------
__device__ __align__(128) float g_x  [ROWS*DMODEL];   // residual stream
__device__ __align__(128) float g_h  [ROWS*DMODEL];   // ln output
__device__ __align__(128) float g_qkv[ROWS*3*DMODEL];
__device__ __align__(128) float g_o  [ROWS*DMODEL];   // attention out
__device__ __align__(128) float g_ff [ROWS*FFDIM];    // mlp hidden

__device__ __forceinline__ float gelu_tanh(float x) {
    const float c = 0.7978845608028654f;
    float x3 = x * x * x;
    return 0.5f * x * (1.0f + tanhf(c * (x + 0.044715f * x3)));
}

// ---------------- optimized fp32 SGEMM ----------------
// C[M,N] = A[M,K] @ B[K,N] (+bias)(+gelu)(+resid)
// EPI: 0 = +bias, 1 = +bias+gelu, 2 = +bias+resid, 3 = plain w/ col guard (stride Nreal)
// BM=BN=128, BK=8, 256 thr, 8x8/thread (4+4 split), smem double buffer + reg prefetch.
template<int EPI>
__global__ void __launch_bounds__(256, 2)
sgemm(const float* __restrict__ A, const float* __restrict__ B,
      const float* __restrict__ bias, const float* __restrict__ resid,
      float* __restrict__ C, int K, int Nreal)
{
    __shared__ float As[2][8][128];
    __shared__ float Bs[2][8][128];

    const int tid = threadIdx.x;
    const int tx = tid & 15, ty = tid >> 4;
    const int blockM = blockIdx.y * 128;
    const int blockN = blockIdx.x * 128;

    // global-load mapping
    const int aRow = tid >> 1;            // 0..127
    const int aCol = (tid & 1) * 4;       // 0 or 4
    const int bRow = tid >> 5;            // 0..7
    const int bCol = (tid & 31) * 4;      // 0..124

    const float* Aptr = A + (size_t)(blockM + aRow) * K + aCol;
    const float* Bptr = B + (size_t)bRow * Nreal + blockN + bCol;

    float acc[8][8];
#pragma unroll
    for (int i = 0; i < 8; i++)
#pragma unroll
        for (int j = 0; j < 8; j++) acc[i][j] = 0.f;

    const int NB = K >> 3;

    // prologue: load tile 0
    float4 ta = *(const float4*)(Aptr);
    float4 tb;
    if (EPI == 3) {
        int c0 = blockN + bCol;
        tb.x = (c0     < Nreal) ? Bptr[0] : 0.f;
        tb.y = (c0 + 1 < Nreal) ? Bptr[1] : 0.f;
        tb.z = (c0 + 2 < Nreal) ? Bptr[2] : 0.f;
        tb.w = (c0 + 3 < Nreal) ? Bptr[3] : 0.f;
    } else {
        tb = *(const float4*)(Bptr);
    }
    As[0][aCol + 0][aRow] = ta.x;
    As[0][aCol + 1][aRow] = ta.y;
    As[0][aCol + 2][aRow] = ta.z;
    As[0][aCol + 3][aRow] = ta.w;
    *(float4*)&Bs[0][bRow][bCol] = tb;
    __syncthreads();

    for (int bk = 0; bk < NB; bk++) {
        const int s = bk & 1;
        // prefetch next tile into registers
        if (bk + 1 < NB) {
            const float* Ap = Aptr + (bk + 1) * 8;
            const float* Bp = Bptr + (size_t)(bk + 1) * 8 * Nreal;
            ta = *(const float4*)(Ap);
            if (EPI == 3) {
                int c0 = blockN + bCol;
                tb.x = (c0     < Nreal) ? Bp[0] : 0.f;
                tb.y = (c0 + 1 < Nreal) ? Bp[1] : 0.f;
                tb.z = (c0 + 2 < Nreal) ? Bp[2] : 0.f;
                tb.w = (c0 + 3 < Nreal) ? Bp[3] : 0.f;
            } else {
                tb = *(const float4*)(Bp);
            }
        }

#pragma unroll
        for (int k = 0; k < 8; k++) {
            float ar[8], br[8];
            *(float4*)&ar[0] = *(const float4*)&As[s][k][ty * 4];
            *(float4*)&ar[4] = *(const float4*)&As[s][k][ty * 4 + 64];
            *(float4*)&br[0] = *(const float4*)&Bs[s][k][tx * 4];
            *(float4*)&br[4] = *(const float4*)&Bs[s][k][tx * 4 + 64];
#pragma unroll
            for (int i = 0; i < 8; i++)
#pragma unroll
                for (int j = 0; j < 8; j++)
                    acc[i][j] = fmaf(ar[i], br[j], acc[i][j]);
        }

        if (bk + 1 < NB) {
            __syncthreads();   // all warps done reading stage s^1
            const int ns = s ^ 1;
            As[ns][aCol + 0][aRow] = ta.x;
            As[ns][aCol + 1][aRow] = ta.y;
            As[ns][aCol + 2][aRow] = ta.z;
            As[ns][aCol + 3][aRow] = ta.w;
            *(float4*)&Bs[ns][bRow][bCol] = tb;
            __syncthreads();
        }
    }

    // ---------------- epilogue ----------------
    float bf[2][4];
    if (EPI != 3) {
#pragma unroll
        for (int jh = 0; jh < 2; jh++) {
            int col = blockN + tx * 4 + jh * 64;
            *(float4*)&bf[jh][0] = *(const float4*)(bias + col);
        }
    }
#pragma unroll
    for (int i = 0; i < 8; i++) {
        int row = blockM + ty * 4 + (i & 3) + (i >> 2) * 64;
#pragma unroll
        for (int jh = 0; jh < 2; jh++) {
            int col = blockN + tx * 4 + jh * 64;
            float v[4];
#pragma unroll
            for (int j = 0; j < 4; j++) {
                v[j] = acc[i][jh * 4 + j];
                if (EPI != 3) v[j] += bf[jh][j];
                if (EPI == 1) v[j] = gelu_tanh(v[j]);
            }
            if (EPI == 2) {
                float4 rv = *(const float4*)(resid + (size_t)row * Nreal + col);
                v[0] += rv.x; v[1] += rv.y; v[2] += rv.z; v[3] += rv.w;
            }
            if (EPI == 3) {
#pragma unroll
                for (int j = 0; j < 4; j++)
                    if (col + j < Nreal) C[(size_t)row * Nreal + col + j] = v[j];
            } else {
                *(float4*)(C + (size_t)row * Nreal + col) = make_float4(v[0], v[1], v[2], v[3]);
            }
        }
    }
}

// ---------------- embedding (split into 2 launches for ncu alignment) ----------------
__global__ void embed_tok_kernel(const int* __restrict__ tok,
                                 const float* __restrict__ te,
                                 float* __restrict__ x) {
    int idx = blockIdx.x * blockDim.x + threadIdx.x;
    if (idx >= ROWS * DMODEL) return;
    int row = idx / DMODEL, d = idx % DMODEL;
    x[idx] = te[(size_t)tok[row] * DMODEL + d];
}
__global__ void embed_pos_kernel(const float* __restrict__ pe, float* __restrict__ x) {
    int idx = blockIdx.x * blockDim.x + threadIdx.x;
    if (idx >= ROWS * DMODEL) return;
    int row = idx / DMODEL, d = idx % DMODEL, s = row % SEQ;
    x[idx] += pe[(size_t)s * DMODEL + d];
}

// ---------------- layernorm ----------------
__global__ void ln_kernel(const float* __restrict__ x,
                          const float* __restrict__ g, const float* __restrict__ b,
                          float* __restrict__ y) {
    int row = blockIdx.x;
    const float* xr = x + (size_t)row * DMODEL;
    __shared__ float red[256];
    int tid = threadIdx.x;

    float s = 0.f;
    for (int i = tid; i < DMODEL; i += 256) s += xr[i];
    red[tid] = s; __syncthreads();
    for (int k = 128; k > 0; k >>= 1) { if (tid < k) red[tid] += red[tid + k]; __syncthreads(); }
    float mean = red[0] * (1.0f / DMODEL);
    __syncthreads();

    float v = 0.f;
    for (int i = tid; i < DMODEL; i += 256) { float d = xr[i] - mean; v += d * d; }
    red[tid] = v; __syncthreads();
    for (int k = 128; k > 0; k >>= 1) { if (tid < k) red[tid] += red[tid + k]; __syncthreads(); }
    float rstd = rsqrtf(red[0] * (1.0f / DMODEL) + 1e-5f);

    float* yr = y + (size_t)row * DMODEL;
    for (int i = tid; i < DMODEL; i += 256)
        yr[i] = (xr[i] - mean) * rstd * g[i] + b[i];
}

// ---------------- attention (fp32, one block per (b,h,q)) ----------------
__global__ void attn_kernel(const float* __restrict__ qkv, float* __restrict__ o) {
    int qi = blockIdx.x, hd = blockIdx.y, b = blockIdx.z;
    int row = b * SEQ + qi;
    int tid = threadIdx.x;

    __shared__ float sq[HDIM];
    __shared__ float sc[SEQ];
    __shared__ float red[128];

    const float* qptr = qkv + (size_t)row * (3 * DMODEL) + hd * HDIM;
    if (tid < HDIM) sq[tid] = qptr[tid];
    __syncthreads();

    for (int k = tid; k < SEQ; k += 128) {
        const float* kptr = qkv + (size_t)(b * SEQ + k) * (3 * DMODEL) + DMODEL + hd * HDIM;
        float s = 0.f;
#pragma unroll
        for (int d = 0; d < HDIM; d++) s += sq[d] * kptr[d];
        sc[k] = s * 0.125f;
    }
    __syncthreads();

    float m = -1e30f;
    for (int k = tid; k < SEQ; k += 128) m = fmaxf(m, sc[k]);
    red[tid] = m; __syncthreads();
    for (int s2 = 64; s2 > 0; s2 >>= 1) { if (tid < s2) red[tid] = fmaxf(red[tid], red[tid + s2]); __syncthreads(); }
    m = red[0];
    __syncthreads();

    float sum = 0.f;
    for (int k = tid; k < SEQ; k += 128) { float e = __expf(sc[k] - m); sc[k] = e; sum += e; }
    red[tid] = sum; __syncthreads();
    for (int s2 = 64; s2 > 0; s2 >>= 1) { if (tid < s2) red[tid] += red[tid + s2]; __syncthreads(); }
    float inv = 1.0f / red[0];
    __syncthreads();

    int d = tid & 63, half = tid >> 6;
    float acc = 0.f;
    const float* vbase = qkv + 2 * DMODEL + hd * HDIM + d;
    for (int k = half * (SEQ / 2); k < (half + 1) * (SEQ / 2); k++)
        acc += sc[k] * vbase[(size_t)(b * SEQ + k) * (3 * DMODEL)];
    red[tid] = acc; __syncthreads();
    if (tid < HDIM)
        o[(size_t)row * DMODEL + hd * HDIM + tid] = (red[tid] + red[tid + 64]) * inv;
}

// ---------------- launch ----------------
extern "C" void kernel_launch(void* const* d_in, const int* in_sizes, int n_in,
                              void* d_out, int out_size) {
    const int*   tokens    = (const int*)  d_in[0];
    const float* tok_embed = (const float*)d_in[1];
    const float* pos_embed = (const float*)d_in[2];
    const float* ln1_g = (const float*)d_in[3];
    const float* ln1_b = (const float*)d_in[4];
    const float* qkv_w = (const float*)d_in[5];
    const float* qkv_b = (const float*)d_in[6];
    const float* proj_w = (const float*)d_in[7];
    const float* proj_b = (const float*)d_in[8];
    const float* ln2_g = (const float*)d_in[9];
    const float* ln2_b = (const float*)d_in[10];
    const float* ff1_w = (const float*)d_in[11];
    const float* ff1_b = (const float*)d_in[12];
    const float* ff2_w = (const float*)d_in[13];
    const float* ff2_b = (const float*)d_in[14];
    const float* lm_w  = (const float*)d_in[15];
    float* out = (float*)d_out;

    float *px, *ph, *pqkv, *po, *pff;
    cudaGetSymbolAddress((void**)&px,   g_x);
    cudaGetSymbolAddress((void**)&ph,   g_h);
    cudaGetSymbolAddress((void**)&pqkv, g_qkv);
    cudaGetSymbolAddress((void**)&po,   g_o);
    cudaGetSymbolAddress((void**)&pff,  g_ff);

    const int EB = (ROWS * DMODEL + 255) / 256;

    for (int l = 0; l < NLAYER; l++) {
        const float* qw = qkv_w + (size_t)l * DMODEL * 3 * DMODEL;
        const float* qb = qkv_b + (size_t)l * 3 * DMODEL;
        const float* pw = proj_w + (size_t)l * DMODEL * DMODEL;
        const float* pb = proj_b + (size_t)l * DMODEL;
        const float* w1 = ff1_w + (size_t)l * DMODEL * FFDIM;
        const float* b1 = ff1_b + (size_t)l * FFDIM;
        const float* w2 = ff2_w + (size_t)l * FFDIM * DMODEL;
        const float* b2 = ff2_b + (size_t)l * DMODEL;

        if (l == 0) {
            // launches 1,2: embedding; 3: ln1; 4: qkv sgemm (ncu captures our #4)
            embed_tok_kernel<<<EB, 256>>>(tokens, tok_embed, px);
            embed_pos_kernel<<<EB, 256>>>(pos_embed, px);
        }
        ln_kernel<<<ROWS, 256>>>(px, ln1_g + l * DMODEL, ln1_b + l * DMODEL, ph);
        sgemm<0><<<dim3(3 * DMODEL / 128, ROWS / 128), 256>>>(
            ph, qw, qb, nullptr, pqkv, DMODEL, 3 * DMODEL);
        attn_kernel<<<dim3(SEQ, NHEAD, BATCH), 128>>>(pqkv, po);
        sgemm<2><<<dim3(DMODEL / 128, ROWS / 128), 256>>>(
            po, pw, pb, px, px, DMODEL, DMODEL);
        ln_kernel<<<ROWS, 256>>>(px, ln2_g + l * DMODEL, ln2_b + l * DMODEL, ph);
        sgemm<1><<<dim3(FFDIM / 128, ROWS / 128), 256>>>(
            ph, w1, b1, nullptr, pff, DMODEL, FFDIM);
        sgemm<2><<<dim3(DMODEL / 128, ROWS / 128), 256>>>(
            pff, w2, b2, px, px, FFDIM, DMODEL);
    }

    // logits = x @ lm_head_w   [2048 x 50257]
    sgemm<3><<<dim3(VPAD / 128, ROWS / 128), 256>>>(
        px, lm_w, nullptr, nullptr, out, DMODEL, VOCAB);
}

// round 11
// speedup vs baseline: 1.3988x; 1.3988x over previous
#include <cuda_runtime.h>
#include <cstdint>

// ---------------- problem constants ----------------
#define BATCH 2
#define SEQ   1024
#define DMODEL 768
#define FFDIM 3072
#define NHEAD 12
#define HDIM  64
#define NLAYER 4
#define VOCAB 50257
#define VPAD  50304          // 393*128, divisible by 128
#define ROWS (BATCH*SEQ)     // 2048

// ---------------- scratch ----------------
__device__ __align__(128) float g_x  [ROWS*DMODEL];
__device__ __align__(128) float g_h  [ROWS*DMODEL];
__device__ __align__(128) float g_qkv[ROWS*3*DMODEL];
__device__ __align__(128) float g_o  [ROWS*DMODEL];
__device__ __align__(128) float g_ff [ROWS*FFDIM];
__device__ __align__(128) float g_wlm[(size_t)DMODEL*VPAD];   // padded lm_head weights

__device__ __forceinline__ float gelu_tanh(float x) {
    const float c = 0.7978845608028654f;
    float x3 = x * x * x;
    return 0.5f * x * (1.0f + tanhf(c * (x + 0.044715f * x3)));
}

// packed f32x2 fused multiply-add:  d.lo += a.lo*b.lo ; d.hi += a.hi*b.hi
#define FMA2(d, a, b) \
    asm("fma.rn.f32x2 %0, %1, %2, %0;" : "+l"(d) : "l"(a), "l"(b))
#define UNPK(lo, hi, p) \
    asm("mov.b64 {%0,%1}, %2;" : "=r"(lo), "=r"(hi) : "l"(p))

// ---------------- fp32 SGEMM with FFMA2 core ----------------
// C[M,Cstride-ish] = A[M,K] @ B[K,*] ; B row stride = Bstride (always 128-divisible here)
// EPI: 0 = +bias, 1 = +bias+gelu, 2 = +bias+resid, 3 = plain, store-guard col<Cstride
// BM=BN=128, BK=8, 256 thr, 8x8/thread. A-pairs packed (2 M-rows), B duplicated in smem.
template<int EPI>
__global__ void __launch_bounds__(256, 2)
sgemm(const float* __restrict__ A, const float* __restrict__ B,
      const float* __restrict__ bias, const float* __restrict__ resid,
      float* __restrict__ C, int K, int Bstride, int Cstride)
{
    __shared__ float As[2][8][128];
    __shared__ float Bs[2][8][256];    // duplicated: Bs[k][2n+e] = B[k][n]

    const int tid = threadIdx.x;
    const int tx = tid & 15, ty = tid >> 4;
    const int blockM = blockIdx.y * 128;
    const int blockN = blockIdx.x * 128;

    const int aRow = tid >> 1;            // 0..127
    const int aCol = (tid & 1) * 4;       // 0 or 4
    const int bRow = tid >> 5;            // 0..7
    const int bCol = (tid & 31) * 4;      // 0..124

    const float* Aptr = A + (size_t)(blockM + aRow) * K + aCol;
    const float* Bptr = B + (size_t)bRow * Bstride + blockN + bCol;

    // acc2[i][j]: packed pair of M-rows (2i, 2i+1 within the thread's 8 rows), column j
    unsigned long long acc2[4][8];
#pragma unroll
    for (int i = 0; i < 4; i++)
#pragma unroll
        for (int j = 0; j < 8; j++) acc2[i][j] = 0ull;

    const int NB = K >> 3;

    // prologue: tile 0
    float4 ta = *(const float4*)(Aptr);
    float4 tb = *(const float4*)(Bptr);
    As[0][aCol + 0][aRow] = ta.x;
    As[0][aCol + 1][aRow] = ta.y;
    As[0][aCol + 2][aRow] = ta.z;
    As[0][aCol + 3][aRow] = ta.w;
    *(float4*)&Bs[0][bRow][2 * bCol]     = make_float4(tb.x, tb.x, tb.y, tb.y);
    *(float4*)&Bs[0][bRow][2 * bCol + 4] = make_float4(tb.z, tb.z, tb.w, tb.w);
    __syncthreads();

    for (int bk = 0; bk < NB; bk++) {
        const int s = bk & 1;
        if (bk + 1 < NB) {
            ta = *(const float4*)(Aptr + (bk + 1) * 8);
            tb = *(const float4*)(Bptr + (size_t)(bk + 1) * 8 * Bstride);
        }

#pragma unroll
        for (int k = 0; k < 8; k++) {
            unsigned long long a2[4], b2[8];
            const float* arow = &As[s][k][ty * 4];
            {
                ulonglong2 p0 = *(const ulonglong2*)(arow);        // rows ty*4+0..3
                ulonglong2 p1 = *(const ulonglong2*)(arow + 64);   // rows ty*4+64..67
                a2[0] = p0.x; a2[1] = p0.y; a2[2] = p1.x; a2[3] = p1.y;
            }
            const float* brow = &Bs[s][k][tx * 8];
            {
                ulonglong2 q0 = *(const ulonglong2*)(brow);        // cols tx*4+0,1 | 2,3
                ulonglong2 q1 = *(const ulonglong2*)(brow + 4);
                ulonglong2 q2 = *(const ulonglong2*)(brow + 128);  // cols tx*4+64..67
                ulonglong2 q3 = *(const ulonglong2*)(brow + 132);
                b2[0] = q0.x; b2[1] = q0.y; b2[2] = q1.x; b2[3] = q1.y;
                b2[4] = q2.x; b2[5] = q2.y; b2[6] = q3.x; b2[7] = q3.y;
            }
#pragma unroll
            for (int i = 0; i < 4; i++)
#pragma unroll
                for (int j = 0; j < 8; j++)
                    FMA2(acc2[i][j], a2[i], b2[j]);
        }

        if (bk + 1 < NB) {
            __syncthreads();
            const int ns = s ^ 1;
            As[ns][aCol + 0][aRow] = ta.x;
            As[ns][aCol + 1][aRow] = ta.y;
            As[ns][aCol + 2][aRow] = ta.z;
            As[ns][aCol + 3][aRow] = ta.w;
            *(float4*)&Bs[ns][bRow][2 * bCol]     = make_float4(tb.x, tb.x, tb.y, tb.y);
            *(float4*)&Bs[ns][bRow][2 * bCol + 4] = make_float4(tb.z, tb.z, tb.w, tb.w);
            __syncthreads();
        }
    }

    // unpack: accf[r][j], r = row index 0..7 (rows ty*4 + (r&3) + (r>>2)*64)
    float accf[8][8];
#pragma unroll
    for (int i = 0; i < 4; i++)
#pragma unroll
        for (int j = 0; j < 8; j++) {
            uint32_t lo, hi;
            UNPK(lo, hi, acc2[i][j]);
            accf[2 * i][j]     = __uint_as_float(lo);
            accf[2 * i + 1][j] = __uint_as_float(hi);
        }
    // accf rows 0..3 = ty*4+0..3 ; rows 4..7 = ty*4+64..67  (i pairs: (0,1),(2,3),(64,65),(66,67))
    // -> remap: accf[r] with r&3 / r>>2 formula holds:
    //    r=0..1 from i=0, r=2..3 from i=1, r=4..5 from i=2, r=6..7 from i=3  ✓

    // ---------------- epilogue ----------------
    float bf[2][4];
    if (EPI != 3) {
#pragma unroll
        for (int jh = 0; jh < 2; jh++)
            *(float4*)&bf[jh][0] = *(const float4*)(bias + blockN + tx * 4 + jh * 64);
    }
#pragma unroll
    for (int r = 0; r < 8; r++) {
        int row = blockM + ty * 4 + (r < 4 ? r : 64 + (r - 4));
#pragma unroll
        for (int jh = 0; jh < 2; jh++) {
            int col = blockN + tx * 4 + jh * 64;
            float v[4];
#pragma unroll
            for (int j = 0; j < 4; j++) {
                v[j] = accf[r][jh * 4 + j];
                if (EPI != 3) v[j] += bf[jh][j];
                if (EPI == 1) v[j] = gelu_tanh(v[j]);
            }
            if (EPI == 2) {
                float4 rv = *(const float4*)(resid + (size_t)row * Cstride + col);
                v[0] += rv.x; v[1] += rv.y; v[2] += rv.z; v[3] += rv.w;
            }
            if (EPI == 3) {
#pragma unroll
                for (int j = 0; j < 4; j++)
                    if (col + j < Cstride) C[(size_t)row * Cstride + col + j] = v[j];
            } else {
                *(float4*)(C + (size_t)row * Cstride + col) = make_float4(v[0], v[1], v[2], v[3]);
            }
        }
    }
}

// ---------------- lm_head weight pad: [768,50257] -> [768,50304] ----------------
__global__ void pad_kernel(const float* __restrict__ W, float* __restrict__ P) {
    int idx = blockIdx.x * 256 + threadIdx.x;
    if (idx >= DMODEL * VPAD) return;
    int k = idx / VPAD, n = idx - k * VPAD;
    P[idx] = (n < VOCAB) ? W[(size_t)k * VOCAB + n] : 0.f;
}

// ---------------- embedding ----------------
__global__ void embed_tok_kernel(const int* __restrict__ tok,
                                 const float* __restrict__ te,
                                 float* __restrict__ x) {
    int idx = blockIdx.x * blockDim.x + threadIdx.x;
    if (idx >= ROWS * DMODEL) return;
    int row = idx / DMODEL, d = idx % DMODEL;
    x[idx] = te[(size_t)tok[row] * DMODEL + d];
}
__global__ void embed_pos_kernel(const float* __restrict__ pe, float* __restrict__ x) {
    int idx = blockIdx.x * blockDim.x + threadIdx.x;
    if (idx >= ROWS * DMODEL) return;
    int row = idx / DMODEL, d = idx % DMODEL, s = row % SEQ;
    x[idx] += pe[(size_t)s * DMODEL + d];
}

// ---------------- layernorm ----------------
__global__ void ln_kernel(const float* __restrict__ x,
                          const float* __restrict__ g, const float* __restrict__ b,
                          float* __restrict__ y) {
    int row = blockIdx.x;
    const float* xr = x + (size_t)row * DMODEL;
    __shared__ float red[256];
    int tid = threadIdx.x;

    float s = 0.f;
    for (int i = tid; i < DMODEL; i += 256) s += xr[i];
    red[tid] = s; __syncthreads();
    for (int k = 128; k > 0; k >>= 1) { if (tid < k) red[tid] += red[tid + k]; __syncthreads(); }
    float mean = red[0] * (1.0f / DMODEL);
    __syncthreads();

    float v = 0.f;
    for (int i = tid; i < DMODEL; i += 256) { float d = xr[i] - mean; v += d * d; }
    red[tid] = v; __syncthreads();
    for (int k = 128; k > 0; k >>= 1) { if (tid < k) red[tid] += red[tid + k]; __syncthreads(); }
    float rstd = rsqrtf(red[0] * (1.0f / DMODEL) + 1e-5f);

    float* yr = y + (size_t)row * DMODEL;
    for (int i = tid; i < DMODEL; i += 256)
        yr[i] = (xr[i] - mean) * rstd * g[i] + b[i];
}

// ---------------- attention (fp32, one block per (b,h,q)) ----------------
__global__ void attn_kernel(const float* __restrict__ qkv, float* __restrict__ o) {
    int qi = blockIdx.x, hd = blockIdx.y, b = blockIdx.z;
    int row = b * SEQ + qi;
    int tid = threadIdx.x;

    __shared__ float sq[HDIM];
    __shared__ float sc[SEQ];
    __shared__ float red[128];

    const float* qptr = qkv + (size_t)row * (3 * DMODEL) + hd * HDIM;
    if (tid < HDIM) sq[tid] = qptr[tid];
    __syncthreads();

    for (int k = tid; k < SEQ; k += 128) {
        const float* kptr = qkv + (size_t)(b * SEQ + k) * (3 * DMODEL) + DMODEL + hd * HDIM;
        float s = 0.f;
#pragma unroll
        for (int d = 0; d < HDIM; d++) s += sq[d] * kptr[d];
        sc[k] = s * 0.125f;
    }
    __syncthreads();

    float m = -1e30f;
    for (int k = tid; k < SEQ; k += 128) m = fmaxf(m, sc[k]);
    red[tid] = m; __syncthreads();
    for (int s2 = 64; s2 > 0; s2 >>= 1) { if (tid < s2) red[tid] = fmaxf(red[tid], red[tid + s2]); __syncthreads(); }
    m = red[0];
    __syncthreads();

    float sum = 0.f;
    for (int k = tid; k < SEQ; k += 128) { float e = __expf(sc[k] - m); sc[k] = e; sum += e; }
    red[tid] = sum; __syncthreads();
    for (int s2 = 64; s2 > 0; s2 >>= 1) { if (tid < s2) red[tid] += red[tid + s2]; __syncthreads(); }
    float inv = 1.0f / red[0];
    __syncthreads();

    int d = tid & 63, half = tid >> 6;
    float acc = 0.f;
    const float* vbase = qkv + 2 * DMODEL + hd * HDIM + d;
    for (int k = half * (SEQ / 2); k < (half + 1) * (SEQ / 2); k++)
        acc += sc[k] * vbase[(size_t)(b * SEQ + k) * (3 * DMODEL)];
    red[tid] = acc; __syncthreads();
    if (tid < HDIM)
        o[(size_t)row * DMODEL + hd * HDIM + tid] = (red[tid] + red[tid + 64]) * inv;
}

// ---------------- launch ----------------
extern "C" void kernel_launch(void* const* d_in, const int* in_sizes, int n_in,
                              void* d_out, int out_size) {
    const int*   tokens    = (const int*)  d_in[0];
    const float* tok_embed = (const float*)d_in[1];
    const float* pos_embed = (const float*)d_in[2];
    const float* ln1_g = (const float*)d_in[3];
    const float* ln1_b = (const float*)d_in[4];
    const float* qkv_w = (const float*)d_in[5];
    const float* qkv_b = (const float*)d_in[6];
    const float* proj_w = (const float*)d_in[7];
    const float* proj_b = (const float*)d_in[8];
    const float* ln2_g = (const float*)d_in[9];
    const float* ln2_b = (const float*)d_in[10];
    const float* ff1_w = (const float*)d_in[11];
    const float* ff1_b = (const float*)d_in[12];
    const float* ff2_w = (const float*)d_in[13];
    const float* ff2_b = (const float*)d_in[14];
    const float* lm_w  = (const float*)d_in[15];
    float* out = (float*)d_out;

    float *px, *ph, *pqkv, *po, *pff, *pwlm;
    cudaGetSymbolAddress((void**)&px,   g_x);
    cudaGetSymbolAddress((void**)&ph,   g_h);
    cudaGetSymbolAddress((void**)&pqkv, g_qkv);
    cudaGetSymbolAddress((void**)&po,   g_o);
    cudaGetSymbolAddress((void**)&pff,  g_ff);
    cudaGetSymbolAddress((void**)&pwlm, g_wlm);

    const int EB = (ROWS * DMODEL + 255) / 256;

    for (int l = 0; l < NLAYER; l++) {
        const float* qw = qkv_w + (size_t)l * DMODEL * 3 * DMODEL;
        const float* qb = qkv_b + (size_t)l * 3 * DMODEL;
        const float* pw = proj_w + (size_t)l * DMODEL * DMODEL;
        const float* pb = proj_b + (size_t)l * DMODEL;
        const float* w1 = ff1_w + (size_t)l * DMODEL * FFDIM;
        const float* b1 = ff1_b + (size_t)l * FFDIM;
        const float* w2 = ff2_w + (size_t)l * FFDIM * DMODEL;
        const float* b2 = ff2_b + (size_t)l * DMODEL;

        if (l == 0) {
            // launches 1,2: embedding; 3: ln1; 4: qkv sgemm (ncu -s5 catches our #4)
            embed_tok_kernel<<<EB, 256>>>(tokens, tok_embed, px);
            embed_pos_kernel<<<EB, 256>>>(pos_embed, px);
        }
        ln_kernel<<<ROWS, 256>>>(px, ln1_g + l * DMODEL, ln1_b + l * DMODEL, ph);
        sgemm<0><<<dim3(3 * DMODEL / 128, ROWS / 128), 256>>>(
            ph, qw, qb, nullptr, pqkv, DMODEL, 3 * DMODEL, 3 * DMODEL);
        attn_kernel<<<dim3(SEQ, NHEAD, BATCH), 128>>>(pqkv, po);
        sgemm<2><<<dim3(DMODEL / 128, ROWS / 128), 256>>>(
            po, pw, pb, px, px, DMODEL, DMODEL, DMODEL);
        ln_kernel<<<ROWS, 256>>>(px, ln2_g + l * DMODEL, ln2_b + l * DMODEL, ph);
        sgemm<1><<<dim3(FFDIM / 128, ROWS / 128), 256>>>(
            ph, w1, b1, nullptr, pff, DMODEL, FFDIM, FFDIM);
        sgemm<2><<<dim3(DMODEL / 128, ROWS / 128), 256>>>(
            pff, w2, b2, px, px, FFDIM, DMODEL, DMODEL);

        if (l == 0) {
            // pad lm_head weights (independent; overlaps nothing critical)
            pad_kernel<<<(DMODEL * VPAD + 255) / 256, 256>>>(lm_w, pwlm);
        }
    }

    // logits = x @ lm_head_w   [2048 x 50257], B padded to stride VPAD
    sgemm<3><<<dim3(VPAD / 128, ROWS / 128), 256>>>(
        px, pwlm, nullptr, nullptr, out, DMODEL, VPAD, VOCAB);
}

// round 13
// speedup vs baseline: 1.6368x; 1.1701x over previous
#include <cuda_runtime.h>
#include <cstdint>

// ---------------- problem constants ----------------
#define BATCH 2
#define SEQ   1024
#define DMODEL 768
#define FFDIM 3072
#define NHEAD 12
#define HDIM  64
#define NLAYER 4
#define VOCAB 50257
#define VPAD  50304          // 393*128, divisible by 128
#define ROWS (BATCH*SEQ)     // 2048

// ---------------- scratch ----------------
__device__ __align__(128) float g_x  [ROWS*DMODEL];
__device__ __align__(128) float g_h  [ROWS*DMODEL];
__device__ __align__(128) float g_qkv[ROWS*3*DMODEL];
__device__ __align__(128) float g_o  [ROWS*DMODEL];
__device__ __align__(128) float g_ff [ROWS*FFDIM];
__device__ __align__(128) float g_wlm[(size_t)DMODEL*VPAD];   // padded lm_head weights

__device__ __forceinline__ float gelu_tanh(float x) {
    const float c = 0.7978845608028654f;
    float x3 = x * x * x;
    return 0.5f * x * (1.0f + tanhf(c * (x + 0.044715f * x3)));
}

// ---------------- fp32 SGEMM (R8 core: proven 29 TF/s) ----------------
// C[M,*] = A[M,K] @ B[K,*] ; B row stride = Bstride (128-divisible always)
// EPI: 0 = +bias, 1 = +bias+gelu, 2 = +bias+resid, 3 = plain, store-guard col<Cstride
// BM=BN=128, BK=8, 256 thr, 8x8/thread (4+4 split), smem double buffer + reg prefetch.
template<int EPI>
__global__ void __launch_bounds__(256, 2)
sgemm(const float* __restrict__ A, const float* __restrict__ B,
      const float* __restrict__ bias, const float* __restrict__ resid,
      float* __restrict__ C, int K, int Bstride, int Cstride)
{
    __shared__ float As[2][8][128];
    __shared__ float Bs[2][8][128];

    const int tid = threadIdx.x;
    const int tx = tid & 15, ty = tid >> 4;
    const int blockM = blockIdx.y * 128;
    const int blockN = blockIdx.x * 128;

    const int aRow = tid >> 1;            // 0..127
    const int aCol = (tid & 1) * 4;       // 0 or 4
    const int bRow = tid >> 5;            // 0..7
    const int bCol = (tid & 31) * 4;      // 0..124

    const float* Aptr = A + (size_t)(blockM + aRow) * K + aCol;
    const float* Bptr = B + (size_t)bRow * Bstride + blockN + bCol;

    float acc[8][8];
#pragma unroll
    for (int i = 0; i < 8; i++)
#pragma unroll
        for (int j = 0; j < 8; j++) acc[i][j] = 0.f;

    const int NB = K >> 3;

    // prologue: load tile 0 (B loads unconditional float4 -- B is always padded)
    float4 ta = *(const float4*)(Aptr);
    float4 tb = *(const float4*)(Bptr);
    As[0][aCol + 0][aRow] = ta.x;
    As[0][aCol + 1][aRow] = ta.y;
    As[0][aCol + 2][aRow] = ta.z;
    As[0][aCol + 3][aRow] = ta.w;
    *(float4*)&Bs[0][bRow][bCol] = tb;
    __syncthreads();

    for (int bk = 0; bk < NB; bk++) {
        const int s = bk & 1;
        if (bk + 1 < NB) {
            ta = *(const float4*)(Aptr + (bk + 1) * 8);
            tb = *(const float4*)(Bptr + (size_t)(bk + 1) * 8 * Bstride);
        }

#pragma unroll
        for (int k = 0; k < 8; k++) {
            float ar[8], br[8];
            *(float4*)&ar[0] = *(const float4*)&As[s][k][ty * 4];
            *(float4*)&ar[4] = *(const float4*)&As[s][k][ty * 4 + 64];
            *(float4*)&br[0] = *(const float4*)&Bs[s][k][tx * 4];
            *(float4*)&br[4] = *(const float4*)&Bs[s][k][tx * 4 + 64];
#pragma unroll
            for (int i = 0; i < 8; i++)
#pragma unroll
                for (int j = 0; j < 8; j++)
                    acc[i][j] = fmaf(ar[i], br[j], acc[i][j]);
        }

        if (bk + 1 < NB) {
            __syncthreads();
            const int ns = s ^ 1;
            As[ns][aCol + 0][aRow] = ta.x;
            As[ns][aCol + 1][aRow] = ta.y;
            As[ns][aCol + 2][aRow] = ta.z;
            As[ns][aCol + 3][aRow] = ta.w;
            *(float4*)&Bs[ns][bRow][bCol] = tb;
            __syncthreads();
        }
    }

    // ---------------- epilogue ----------------
    float bf[2][4];
    if (EPI != 3) {
#pragma unroll
        for (int jh = 0; jh < 2; jh++)
            *(float4*)&bf[jh][0] = *(const float4*)(bias + blockN + tx * 4 + jh * 64);
    }
#pragma unroll
    for (int i = 0; i < 8; i++) {
        int row = blockM + ty * 4 + (i & 3) + (i >> 2) * 64;
#pragma unroll
        for (int jh = 0; jh < 2; jh++) {
            int col = blockN + tx * 4 + jh * 64;
            float v[4];
#pragma unroll
            for (int j = 0; j < 4; j++) {
                v[j] = acc[i][jh * 4 + j];
                if (EPI != 3) v[j] += bf[jh][j];
                if (EPI == 1) v[j] = gelu_tanh(v[j]);
            }
            if (EPI == 2) {
                float4 rv = *(const float4*)(resid + (size_t)row * Cstride + col);
                v[0] += rv.x; v[1] += rv.y; v[2] += rv.z; v[3] += rv.w;
            }
            if (EPI == 3) {
#pragma unroll
                for (int j = 0; j < 4; j++)
                    if (col + j < Cstride) C[(size_t)row * Cstride + col + j] = v[j];
            } else {
                *(float4*)(C + (size_t)row * Cstride + col) = make_float4(v[0], v[1], v[2], v[3]);
            }
        }
    }
}

// ---------------- lm_head weight pad: [768,50257] -> [768,50304] ----------------
__global__ void pad_kernel(const float* __restrict__ W, float* __restrict__ P) {
    int idx = blockIdx.x * 256 + threadIdx.x;
    if (idx >= DMODEL * VPAD) return;
    int k = idx / VPAD, n = idx - k * VPAD;
    P[idx] = (n < VOCAB) ? W[(size_t)k * VOCAB + n] : 0.f;
}

// ---------------- embedding ----------------
__global__ void embed_tok_kernel(const int* __restrict__ tok,
                                 const float* __restrict__ te,
                                 float* __restrict__ x) {
    int idx = blockIdx.x * blockDim.x + threadIdx.x;
    if (idx >= ROWS * DMODEL) return;
    int row = idx / DMODEL, d = idx % DMODEL;
    x[idx] = te[(size_t)tok[row] * DMODEL + d];
}
__global__ void embed_pos_kernel(const float* __restrict__ pe, float* __restrict__ x) {
    int idx = blockIdx.x * blockDim.x + threadIdx.x;
    if (idx >= ROWS * DMODEL) return;
    int row = idx / DMODEL, d = idx % DMODEL, s = row % SEQ;
    x[idx] += pe[(size_t)s * DMODEL + d];
}

// ---------------- layernorm ----------------
__global__ void ln_kernel(const float* __restrict__ x,
                          const float* __restrict__ g, const float* __restrict__ b,
                          float* __restrict__ y) {
    int row = blockIdx.x;
    const float* xr = x + (size_t)row * DMODEL;
    __shared__ float red[256];
    int tid = threadIdx.x;

    float s = 0.f;
    for (int i = tid; i < DMODEL; i += 256) s += xr[i];
    red[tid] = s; __syncthreads();
    for (int k = 128; k > 0; k >>= 1) { if (tid < k) red[tid] += red[tid + k]; __syncthreads(); }
    float mean = red[0] * (1.0f / DMODEL);
    __syncthreads();

    float v = 0.f;
    for (int i = tid; i < DMODEL; i += 256) { float d = xr[i] - mean; v += d * d; }
    red[tid] = v; __syncthreads();
    for (int k = 128; k > 0; k >>= 1) { if (tid < k) red[tid] += red[tid + k]; __syncthreads(); }
    float rstd = rsqrtf(red[0] * (1.0f / DMODEL) + 1e-5f);

    float* yr = y + (size_t)row * DMODEL;
    for (int i = tid; i < DMODEL; i += 256)
        yr[i] = (xr[i] - mean) * rstd * g[i] + b[i];
}

// ---------------- attention (fp32, one block per (b,h,q)) ----------------
__global__ void attn_kernel(const float* __restrict__ qkv, float* __restrict__ o) {
    int qi = blockIdx.x, hd = blockIdx.y, b = blockIdx.z;
    int row = b * SEQ + qi;
    int tid = threadIdx.x;

    __shared__ float sq[HDIM];
    __shared__ float sc[SEQ];
    __shared__ float red[128];

    const float* qptr = qkv + (size_t)row * (3 * DMODEL) + hd * HDIM;
    if (tid < HDIM) sq[tid] = qptr[tid];
    __syncthreads();

    for (int k = tid; k < SEQ; k += 128) {
        const float* kptr = qkv + (size_t)(b * SEQ + k) * (3 * DMODEL) + DMODEL + hd * HDIM;
        float s = 0.f;
#pragma unroll
        for (int d = 0; d < HDIM; d++) s += sq[d] * kptr[d];
        sc[k] = s * 0.125f;
    }
    __syncthreads();

    float m = -1e30f;
    for (int k = tid; k < SEQ; k += 128) m = fmaxf(m, sc[k]);
    red[tid] = m; __syncthreads();
    for (int s2 = 64; s2 > 0; s2 >>= 1) { if (tid < s2) red[tid] = fmaxf(red[tid], red[tid + s2]); __syncthreads(); }
    m = red[0];
    __syncthreads();

    float sum = 0.f;
    for (int k = tid; k < SEQ; k += 128) { float e = __expf(sc[k] - m); sc[k] = e; sum += e; }
    red[tid] = sum; __syncthreads();
    for (int s2 = 64; s2 > 0; s2 >>= 1) { if (tid < s2) red[tid] += red[tid + s2]; __syncthreads(); }
    float inv = 1.0f / red[0];
    __syncthreads();

    int d = tid & 63, half = tid >> 6;
    float acc = 0.f;
    const float* vbase = qkv + 2 * DMODEL + hd * HDIM + d;
    for (int k = half * (SEQ / 2); k < (half + 1) * (SEQ / 2); k++)
        acc += sc[k] * vbase[(size_t)(b * SEQ + k) * (3 * DMODEL)];
    red[tid] = acc; __syncthreads();
    if (tid < HDIM)
        o[(size_t)row * DMODEL + hd * HDIM + tid] = (red[tid] + red[tid + 64]) * inv;
}

// ---------------- launch ----------------
extern "C" void kernel_launch(void* const* d_in, const int* in_sizes, int n_in,
                              void* d_out, int out_size) {
    const int*   tokens    = (const int*)  d_in[0];
    const float* tok_embed = (const float*)d_in[1];
    const float* pos_embed = (const float*)d_in[2];
    const float* ln1_g = (const float*)d_in[3];
    const float* ln1_b = (const float*)d_in[4];
    const float* qkv_w = (const float*)d_in[5];
    const float* qkv_b = (const float*)d_in[6];
    const float* proj_w = (const float*)d_in[7];
    const float* proj_b = (const float*)d_in[8];
    const float* ln2_g = (const float*)d_in[9];
    const float* ln2_b = (const float*)d_in[10];
    const float* ff1_w = (const float*)d_in[11];
    const float* ff1_b = (const float*)d_in[12];
    const float* ff2_w = (const float*)d_in[13];
    const float* ff2_b = (const float*)d_in[14];
    const float* lm_w  = (const float*)d_in[15];
    float* out = (float*)d_out;

    float *px, *ph, *pqkv, *po, *pff, *pwlm;
    cudaGetSymbolAddress((void**)&px,   g_x);
    cudaGetSymbolAddress((void**)&ph,   g_h);
    cudaGetSymbolAddress((void**)&pqkv, g_qkv);
    cudaGetSymbolAddress((void**)&po,   g_o);
    cudaGetSymbolAddress((void**)&pff,  g_ff);
    cudaGetSymbolAddress((void**)&pwlm, g_wlm);

    const int EB = (ROWS * DMODEL + 255) / 256;

    for (int l = 0; l < NLAYER; l++) {
        const float* qw = qkv_w + (size_t)l * DMODEL * 3 * DMODEL;
        const float* qb = qkv_b + (size_t)l * 3 * DMODEL;
        const float* pw = proj_w + (size_t)l * DMODEL * DMODEL;
        const float* pb = proj_b + (size_t)l * DMODEL;
        const float* w1 = ff1_w + (size_t)l * DMODEL * FFDIM;
        const float* b1 = ff1_b + (size_t)l * FFDIM;
        const float* w2 = ff2_w + (size_t)l * FFDIM * DMODEL;
        const float* b2 = ff2_b + (size_t)l * DMODEL;

        if (l == 0) {
            // launches 1,2: embedding; 3: ln1; 4: qkv sgemm (ncu -s5 catches our #4)
            embed_tok_kernel<<<EB, 256>>>(tokens, tok_embed, px);
            embed_pos_kernel<<<EB, 256>>>(pos_embed, px);
        }
        ln_kernel<<<ROWS, 256>>>(px, ln1_g + l * DMODEL, ln1_b + l * DMODEL, ph);
        sgemm<0><<<dim3(3 * DMODEL / 128, ROWS / 128), 256>>>(
            ph, qw, qb, nullptr, pqkv, DMODEL, 3 * DMODEL, 3 * DMODEL);
        attn_kernel<<<dim3(SEQ, NHEAD, BATCH), 128>>>(pqkv, po);
        sgemm<2><<<dim3(DMODEL / 128, ROWS / 128), 256>>>(
            po, pw, pb, px, px, DMODEL, DMODEL, DMODEL);
        ln_kernel<<<ROWS, 256>>>(px, ln2_g + l * DMODEL, ln2_b + l * DMODEL, ph);
        sgemm<1><<<dim3(FFDIM / 128, ROWS / 128), 256>>>(
            ph, w1, b1, nullptr, pff, DMODEL, FFDIM, FFDIM);
        sgemm<2><<<dim3(DMODEL / 128, ROWS / 128), 256>>>(
            pff, w2, b2, px, px, FFDIM, DMODEL, DMODEL);

        if (l == 0) {
            // pad lm_head weights (independent; overlaps the layer stream)
            pad_kernel<<<(DMODEL * VPAD + 255) / 256, 256>>>(lm_w, pwlm);
        }
    }

    // logits = x @ lm_head_w   [2048 x 50257], B padded to stride VPAD
    sgemm<3><<<dim3(VPAD / 128, ROWS / 128), 256>>>(
        px, pwlm, nullptr, nullptr, out, DMODEL, VPAD, VOCAB);
}

// round 15
// speedup vs baseline: 6.3614x; 3.8864x over previous
#include <cuda_runtime.h>
#include <cstdint>

// ---------------- problem constants ----------------
#define BATCH 2
#define SEQ   1024
#define DMODEL 768
#define FFDIM 3072
#define NHEAD 12
#define HDIM  64
#define NLAYER 4
#define VOCAB 50257
#define VPAD  50304          // 393*128, divisible by 128
#define ROWS (BATCH*SEQ)     // 2048

// ---------------- scratch ----------------
__device__ __align__(128) float g_x  [ROWS*DMODEL];
__device__ __align__(128) float g_h  [ROWS*DMODEL];
__device__ __align__(128) float g_qkv[ROWS*3*DMODEL];
__device__ __align__(128) float g_o  [ROWS*DMODEL];
__device__ __align__(128) float g_ff [ROWS*FFDIM];
__device__ __align__(128) float g_wlm[(size_t)DMODEL*VPAD];   // padded lm_head weights

__device__ __forceinline__ float gelu_tanh(float x) {
    const float c = 0.7978845608028654f;
    float x3 = x * x * x;
    return 0.5f * x * (1.0f + tanhf(c * (x + 0.044715f * x3)));
}

// ---------------- fp32 SGEMM (proven core) ----------------
// EPI: 0 = +bias, 1 = +bias+gelu, 2 = +bias+resid, 3 = plain, store-guard col<Cstride
template<int EPI>
__global__ void __launch_bounds__(256, 2)
sgemm(const float* __restrict__ A, const float* __restrict__ B,
      const float* __restrict__ bias, const float* __restrict__ resid,
      float* __restrict__ C, int K, int Bstride, int Cstride)
{
    __shared__ float As[2][8][128];
    __shared__ float Bs[2][8][128];

    const int tid = threadIdx.x;
    const int tx = tid & 15, ty = tid >> 4;
    const int blockM = blockIdx.y * 128;
    const int blockN = blockIdx.x * 128;

    const int aRow = tid >> 1;
    const int aCol = (tid & 1) * 4;
    const int bRow = tid >> 5;
    const int bCol = (tid & 31) * 4;

    const float* Aptr = A + (size_t)(blockM + aRow) * K + aCol;
    const float* Bptr = B + (size_t)bRow * Bstride + blockN + bCol;

    float acc[8][8];
#pragma unroll
    for (int i = 0; i < 8; i++)
#pragma unroll
        for (int j = 0; j < 8; j++) acc[i][j] = 0.f;

    const int NB = K >> 3;

    float4 ta = *(const float4*)(Aptr);
    float4 tb = *(const float4*)(Bptr);
    As[0][aCol + 0][aRow] = ta.x;
    As[0][aCol + 1][aRow] = ta.y;
    As[0][aCol + 2][aRow] = ta.z;
    As[0][aCol + 3][aRow] = ta.w;
    *(float4*)&Bs[0][bRow][bCol] = tb;
    __syncthreads();

    for (int bk = 0; bk < NB; bk++) {
        const int s = bk & 1;
        if (bk + 1 < NB) {
            ta = *(const float4*)(Aptr + (bk + 1) * 8);
            tb = *(const float4*)(Bptr + (size_t)(bk + 1) * 8 * Bstride);
        }

#pragma unroll
        for (int k = 0; k < 8; k++) {
            float ar[8], br[8];
            *(float4*)&ar[0] = *(const float4*)&As[s][k][ty * 4];
            *(float4*)&ar[4] = *(const float4*)&As[s][k][ty * 4 + 64];
            *(float4*)&br[0] = *(const float4*)&Bs[s][k][tx * 4];
            *(float4*)&br[4] = *(const float4*)&Bs[s][k][tx * 4 + 64];
#pragma unroll
            for (int i = 0; i < 8; i++)
#pragma unroll
                for (int j = 0; j < 8; j++)
                    acc[i][j] = fmaf(ar[i], br[j], acc[i][j]);
        }

        if (bk + 1 < NB) {
            __syncthreads();
            const int ns = s ^ 1;
            As[ns][aCol + 0][aRow] = ta.x;
            As[ns][aCol + 1][aRow] = ta.y;
            As[ns][aCol + 2][aRow] = ta.z;
            As[ns][aCol + 3][aRow] = ta.w;
            *(float4*)&Bs[ns][bRow][bCol] = tb;
            __syncthreads();
        }
    }

    float bf[2][4];
    if (EPI != 3) {
#pragma unroll
        for (int jh = 0; jh < 2; jh++)
            *(float4*)&bf[jh][0] = *(const float4*)(bias + blockN + tx * 4 + jh * 64);
    }
#pragma unroll
    for (int i = 0; i < 8; i++) {
        int row = blockM + ty * 4 + (i & 3) + (i >> 2) * 64;
#pragma unroll
        for (int jh = 0; jh < 2; jh++) {
            int col = blockN + tx * 4 + jh * 64;
            float v[4];
#pragma unroll
            for (int j = 0; j < 4; j++) {
                v[j] = acc[i][jh * 4 + j];
                if (EPI != 3) v[j] += bf[jh][j];
                if (EPI == 1) v[j] = gelu_tanh(v[j]);
            }
            if (EPI == 2) {
                float4 rv = *(const float4*)(resid + (size_t)row * Cstride + col);
                v[0] += rv.x; v[1] += rv.y; v[2] += rv.z; v[3] += rv.w;
            }
            if (EPI == 3) {
#pragma unroll
                for (int j = 0; j < 4; j++)
                    if (col + j < Cstride) C[(size_t)row * Cstride + col + j] = v[j];
            } else {
                *(float4*)(C + (size_t)row * Cstride + col) = make_float4(v[0], v[1], v[2], v[3]);
            }
        }
    }
}

// ---------------- flash-style attention ----------------
// grid (SEQ/64, NHEAD, BATCH), 256 threads, dynamic smem.
// Q tile 64x64 (pre-scaled), K tiles 64 keys staged transposed, online softmax, PV accum.
#define AQ 64          // query tile
#define AK 64          // key tile
#define APITCH 68      // smem row pitch (floats): 272B, 16B-aligned, bank-staggered
#define QS_OFF 0
#define KS_OFF (64*APITCH)
#define VS_OFF (2*64*APITCH)
#define PS_OFF (3*64*APITCH)
#define ATT_SMEM (4*64*APITCH*4)   // 69632 bytes

__global__ void __launch_bounds__(256, 1)
attn_kernel(const float* __restrict__ qkv, float* __restrict__ o)
{
    extern __shared__ float sm[];
    const int tid = threadIdx.x;
    const int tx = tid & 15, ty = tid >> 4;
    const int q0 = blockIdx.x * AQ;
    const int h  = blockIdx.y;
    const int b  = blockIdx.z;

    const size_t rowstride = 3 * DMODEL;
    const float* Qg = qkv + (size_t)(b * SEQ) * rowstride + h * HDIM;          // + q*rowstride + d
    const float* Kg = Qg + DMODEL;
    const float* Vg = Qg + 2 * DMODEL;

    // load Q tile transposed+scaled: Qs[d][q] = Q[q0+q][d] * 0.125
#pragma unroll
    for (int it = 0; it < 4; it++) {
        int i = tid + it * 256;               // 0..1023
        int q = i >> 4, d = (i & 15) * 4;
        float4 v = *(const float4*)(Qg + (size_t)(q0 + q) * rowstride + d);
        sm[QS_OFF + (d + 0) * APITCH + q] = v.x * 0.125f;
        sm[QS_OFF + (d + 1) * APITCH + q] = v.y * 0.125f;
        sm[QS_OFF + (d + 2) * APITCH + q] = v.z * 0.125f;
        sm[QS_OFF + (d + 3) * APITCH + q] = v.w * 0.125f;
    }

    float acc_o[4][4];
    float mrow[4], lrow[4];
#pragma unroll
    for (int i = 0; i < 4; i++) {
        mrow[i] = -1e30f; lrow[i] = 0.f;
#pragma unroll
        for (int j = 0; j < 4; j++) acc_o[i][j] = 0.f;
    }

    for (int kt = 0; kt < SEQ / AK; kt++) {
        __syncthreads();   // prev PV done (Vs/Ks reusable), Q ready on first iter
        // load K tile transposed: Ks[d][k]; V tile native: Vs[k][d]
#pragma unroll
        for (int it = 0; it < 4; it++) {
            int i = tid + it * 256;
            int k = i >> 4, d = (i & 15) * 4;
            const float* kp = Kg + (size_t)(kt * AK + k) * rowstride + d;
            float4 kv = *(const float4*)(kp);
            sm[KS_OFF + (d + 0) * APITCH + k] = kv.x;
            sm[KS_OFF + (d + 1) * APITCH + k] = kv.y;
            sm[KS_OFF + (d + 2) * APITCH + k] = kv.z;
            sm[KS_OFF + (d + 3) * APITCH + k] = kv.w;
            float4 vv = *(const float4*)(Vg + (size_t)(kt * AK + k) * rowstride + d);
            *(float4*)&sm[VS_OFF + k * APITCH + d] = vv;
        }
        __syncthreads();

        // S = Q^T K  (thread: 4q x 4k)
        float s4[4][4];
#pragma unroll
        for (int i = 0; i < 4; i++)
#pragma unroll
            for (int j = 0; j < 4; j++) s4[i][j] = 0.f;
#pragma unroll
        for (int d = 0; d < HDIM; d++) {
            float qr[4], kr[4];
            *(float4*)qr = *(const float4*)&sm[QS_OFF + d * APITCH + ty * 4];
            *(float4*)kr = *(const float4*)&sm[KS_OFF + d * APITCH + tx * 4];
#pragma unroll
            for (int i = 0; i < 4; i++)
#pragma unroll
                for (int j = 0; j < 4; j++)
                    s4[i][j] = fmaf(qr[i], kr[j], s4[i][j]);
        }

        // online softmax per q-row (reduce across 16 tx lanes)
#pragma unroll
        for (int i = 0; i < 4; i++) {
            float tm = fmaxf(fmaxf(s4[i][0], s4[i][1]), fmaxf(s4[i][2], s4[i][3]));
#pragma unroll
            for (int off = 8; off > 0; off >>= 1)
                tm = fmaxf(tm, __shfl_xor_sync(0xFFFFFFFFu, tm, off, 16));
            float nm = fmaxf(mrow[i], tm);
            float corr = __expf(mrow[i] - nm);
            mrow[i] = nm;
            float rs = 0.f;
#pragma unroll
            for (int j = 0; j < 4; j++) {
                s4[i][j] = __expf(s4[i][j] - nm);
                rs += s4[i][j];
            }
#pragma unroll
            for (int off = 8; off > 0; off >>= 1)
                rs += __shfl_xor_sync(0xFFFFFFFFu, rs, off, 16);
            lrow[i] = lrow[i] * corr + rs;
#pragma unroll
            for (int j = 0; j < 4; j++) acc_o[i][j] *= corr;
        }

        // stage P transposed: Ps[k][q]  (float4 over q)
#pragma unroll
        for (int j = 0; j < 4; j++) {
            float4 pv = make_float4(s4[0][j], s4[1][j], s4[2][j], s4[3][j]);
            *(float4*)&sm[PS_OFF + (tx * 4 + j) * APITCH + ty * 4] = pv;
        }
        __syncthreads();

        // O += P V  (thread: 4q x 4d; scalar P broadcast, float4 V)
#pragma unroll 4
        for (int k = 0; k < AK; k++) {
            float vr[4];
            *(float4*)vr = *(const float4*)&sm[VS_OFF + k * APITCH + tx * 4];
            float pq[4];
            pq[0] = sm[PS_OFF + k * APITCH + ty * 4 + 0];
            pq[1] = sm[PS_OFF + k * APITCH + ty * 4 + 1];
            pq[2] = sm[PS_OFF + k * APITCH + ty * 4 + 2];
            pq[3] = sm[PS_OFF + k * APITCH + ty * 4 + 3];
#pragma unroll
            for (int i = 0; i < 4; i++)
#pragma unroll
                for (int j = 0; j < 4; j++)
                    acc_o[i][j] = fmaf(pq[i], vr[j], acc_o[i][j]);
        }
    }

    // write O / l
#pragma unroll
    for (int i = 0; i < 4; i++) {
        float inv = 1.0f / lrow[i];
        int row = b * SEQ + q0 + ty * 4 + i;
        float4 ov = make_float4(acc_o[i][0] * inv, acc_o[i][1] * inv,
                                acc_o[i][2] * inv, acc_o[i][3] * inv);
        *(float4*)(o + (size_t)row * DMODEL + h * HDIM + tx * 4) = ov;
    }
}

// ---------------- lm_head weight pad ----------------
__global__ void pad_kernel(const float* __restrict__ W, float* __restrict__ P) {
    int idx = blockIdx.x * 256 + threadIdx.x;
    if (idx >= DMODEL * VPAD) return;
    int k = idx / VPAD, n = idx - k * VPAD;
    P[idx] = (n < VOCAB) ? W[(size_t)k * VOCAB + n] : 0.f;
}

// ---------------- embedding ----------------
__global__ void embed_tok_kernel(const int* __restrict__ tok,
                                 const float* __restrict__ te,
                                 float* __restrict__ x) {
    int idx = blockIdx.x * blockDim.x + threadIdx.x;
    if (idx >= ROWS * DMODEL) return;
    int row = idx / DMODEL, d = idx % DMODEL;
    x[idx] = te[(size_t)tok[row] * DMODEL + d];
}
__global__ void embed_pos_kernel(const float* __restrict__ pe, float* __restrict__ x) {
    int idx = blockIdx.x * blockDim.x + threadIdx.x;
    if (idx >= ROWS * DMODEL) return;
    int row = idx / DMODEL, d = idx % DMODEL, s = row % SEQ;
    x[idx] += pe[(size_t)s * DMODEL + d];
}

// ---------------- layernorm ----------------
__global__ void ln_kernel(const float* __restrict__ x,
                          const float* __restrict__ g, const float* __restrict__ b,
                          float* __restrict__ y) {
    int row = blockIdx.x;
    const float* xr = x + (size_t)row * DMODEL;
    __shared__ float red[256];
    int tid = threadIdx.x;

    float s = 0.f;
    for (int i = tid; i < DMODEL; i += 256) s += xr[i];
    red[tid] = s; __syncthreads();
    for (int k = 128; k > 0; k >>= 1) { if (tid < k) red[tid] += red[tid + k]; __syncthreads(); }
    float mean = red[0] * (1.0f / DMODEL);
    __syncthreads();

    float v = 0.f;
    for (int i = tid; i < DMODEL; i += 256) { float d = xr[i] - mean; v += d * d; }
    red[tid] = v; __syncthreads();
    for (int k = 128; k > 0; k >>= 1) { if (tid < k) red[tid] += red[tid + k]; __syncthreads(); }
    float rstd = rsqrtf(red[0] * (1.0f / DMODEL) + 1e-5f);

    float* yr = y + (size_t)row * DMODEL;
    for (int i = tid; i < DMODEL; i += 256)
        yr[i] = (xr[i] - mean) * rstd * g[i] + b[i];
}

// ---------------- launch ----------------
extern "C" void kernel_launch(void* const* d_in, const int* in_sizes, int n_in,
                              void* d_out, int out_size) {
    const int*   tokens    = (const int*)  d_in[0];
    const float* tok_embed = (const float*)d_in[1];
    const float* pos_embed = (const float*)d_in[2];
    const float* ln1_g = (const float*)d_in[3];
    const float* ln1_b = (const float*)d_in[4];
    const float* qkv_w = (const float*)d_in[5];
    const float* qkv_b = (const float*)d_in[6];
    const float* proj_w = (const float*)d_in[7];
    const float* proj_b = (const float*)d_in[8];
    const float* ln2_g = (const float*)d_in[9];
    const float* ln2_b = (const float*)d_in[10];
    const float* ff1_w = (const float*)d_in[11];
    const float* ff1_b = (const float*)d_in[12];
    const float* ff2_w = (const float*)d_in[13];
    const float* ff2_b = (const float*)d_in[14];
    const float* lm_w  = (const float*)d_in[15];
    float* out = (float*)d_out;

    float *px, *ph, *pqkv, *po, *pff, *pwlm;
    cudaGetSymbolAddress((void**)&px,   g_x);
    cudaGetSymbolAddress((void**)&ph,   g_h);
    cudaGetSymbolAddress((void**)&pqkv, g_qkv);
    cudaGetSymbolAddress((void**)&po,   g_o);
    cudaGetSymbolAddress((void**)&pff,  g_ff);
    cudaGetSymbolAddress((void**)&pwlm, g_wlm);

    cudaFuncSetAttribute(attn_kernel, cudaFuncAttributeMaxDynamicSharedMemorySize, ATT_SMEM);

    const int EB = (ROWS * DMODEL + 255) / 256;

    for (int l = 0; l < NLAYER; l++) {
        const float* qw = qkv_w + (size_t)l * DMODEL * 3 * DMODEL;
        const float* qb = qkv_b + (size_t)l * 3 * DMODEL;
        const float* pw = proj_w + (size_t)l * DMODEL * DMODEL;
        const float* pb = proj_b + (size_t)l * DMODEL;
        const float* w1 = ff1_w + (size_t)l * DMODEL * FFDIM;
        const float* b1 = ff1_b + (size_t)l * FFDIM;
        const float* w2 = ff2_w + (size_t)l * FFDIM * DMODEL;
        const float* b2 = ff2_b + (size_t)l * DMODEL;

        if (l == 0) {
            embed_tok_kernel<<<EB, 256>>>(tokens, tok_embed, px);
            embed_pos_kernel<<<EB, 256>>>(pos_embed, px);
        }
        ln_kernel<<<ROWS, 256>>>(px, ln1_g + l * DMODEL, ln1_b + l * DMODEL, ph);
        sgemm<0><<<dim3(3 * DMODEL / 128, ROWS / 128), 256>>>(
            ph, qw, qb, nullptr, pqkv, DMODEL, 3 * DMODEL, 3 * DMODEL);
        attn_kernel<<<dim3(SEQ / AQ, NHEAD, BATCH), 256, ATT_SMEM>>>(pqkv, po);
        sgemm<2><<<dim3(DMODEL / 128, ROWS / 128), 256>>>(
            po, pw, pb, px, px, DMODEL, DMODEL, DMODEL);
        ln_kernel<<<ROWS, 256>>>(px, ln2_g + l * DMODEL, ln2_b + l * DMODEL, ph);
        sgemm<1><<<dim3(FFDIM / 128, ROWS / 128), 256>>>(
            ph, w1, b1, nullptr, pff, DMODEL, FFDIM, FFDIM);
        sgemm<2><<<dim3(DMODEL / 128, ROWS / 128), 256>>>(
            pff, w2, b2, px, px, FFDIM, DMODEL, DMODEL);

        if (l == 0) {
            pad_kernel<<<(DMODEL * VPAD + 255) / 256, 256>>>(lm_w, pwlm);
        }
    }

    // logits = x @ lm_head_w   [2048 x 50257], B padded to stride VPAD
    sgemm<3><<<dim3(VPAD / 128, ROWS / 128), 256>>>(
        px, pwlm, nullptr, nullptr, out, DMODEL, VPAD, VOCAB);
}

// round 16
// speedup vs baseline: 7.1806x; 1.1288x over previous
#include <cuda_runtime.h>
#include <cstdint>

// ---------------- problem constants ----------------
#define BATCH 2
#define SEQ   1024
#define DMODEL 768
#define FFDIM 3072
#define NHEAD 12
#define HDIM  64
#define NLAYER 4
#define VOCAB 50257
#define VPAD  50304          // 393*128, divisible by 128
#define ROWS (BATCH*SEQ)     // 2048

// ---------------- scratch ----------------
__device__ __align__(128) float g_x  [ROWS*DMODEL];
__device__ __align__(128) float g_h  [ROWS*DMODEL];
__device__ __align__(128) float g_qkv[ROWS*3*DMODEL];
__device__ __align__(128) float g_o  [ROWS*DMODEL];
__device__ __align__(128) float g_ff [ROWS*FFDIM];
__device__ __align__(128) float g_wlm[(size_t)DMODEL*VPAD];   // padded lm_head weights

__device__ __forceinline__ float gelu_tanh(float x) {
    const float c = 0.7978845608028654f;
    float x3 = x * x * x;
    return 0.5f * x * (1.0f + tanhf(c * (x + 0.044715f * x3)));
}

// packed f32x2 FMA: d.lo += a.lo*b.lo ; d.hi += a.hi*b.hi  (element-wise rn fma)
#define FMA2(d, a, b) \
    asm("fma.rn.f32x2 %0, %1, %2, %0;" : "+l"(d) : "l"(a), "l"(b))
#define PACK_DUP(d, f) \
    asm("mov.b64 %0, {%1,%1};" : "=l"(d) : "r"(__float_as_uint(f)))
#define UNPK(lo, hi, p) \
    asm("mov.b64 {%0,%1}, %2;" : "=r"(lo), "=r"(hi) : "l"(p))

// ---------------- fp32 SGEMM, FFMA2 over column pairs ----------------
// C[M,*] = A[M,K] @ B[K,*] ; B row stride = Bstride (128-divisible)
// EPI: 0 = +bias, 1 = +bias+gelu, 2 = +bias+resid, 3 = plain, store-guard col<Cstride
// BM=BN=128, BK=8, 256 thr, 8x8/thread. Smem layout IDENTICAL to the proven R8 core;
// only the inner product packs adjacent N columns into f32x2 lanes.
template<int EPI>
__global__ void __launch_bounds__(256, 2)
sgemm(const float* __restrict__ A, const float* __restrict__ B,
      const float* __restrict__ bias, const float* __restrict__ resid,
      float* __restrict__ C, int K, int Bstride, int Cstride)
{
    __shared__ float As[2][8][128];
    __shared__ float Bs[2][8][128];

    const int tid = threadIdx.x;
    const int tx = tid & 15, ty = tid >> 4;
    const int blockM = blockIdx.y * 128;
    const int blockN = blockIdx.x * 128;

    const int aRow = tid >> 1;
    const int aCol = (tid & 1) * 4;
    const int bRow = tid >> 5;
    const int bCol = (tid & 31) * 4;

    const float* Aptr = A + (size_t)(blockM + aRow) * K + aCol;
    const float* Bptr = B + (size_t)bRow * Bstride + blockN + bCol;

    // acc2[i][p]: row i (8 rows), column pair p (4 pairs = 8 cols)
    unsigned long long acc2[8][4];
#pragma unroll
    for (int i = 0; i < 8; i++)
#pragma unroll
        for (int p = 0; p < 4; p++) acc2[i][p] = 0ull;

    const int NB = K >> 3;

    float4 ta = *(const float4*)(Aptr);
    float4 tb = *(const float4*)(Bptr);
    As[0][aCol + 0][aRow] = ta.x;
    As[0][aCol + 1][aRow] = ta.y;
    As[0][aCol + 2][aRow] = ta.z;
    As[0][aCol + 3][aRow] = ta.w;
    *(float4*)&Bs[0][bRow][bCol] = tb;
    __syncthreads();

    for (int bk = 0; bk < NB; bk++) {
        const int s = bk & 1;
        if (bk + 1 < NB) {
            ta = *(const float4*)(Aptr + (bk + 1) * 8);
            tb = *(const float4*)(Bptr + (size_t)(bk + 1) * 8 * Bstride);
        }

#pragma unroll
        for (int k = 0; k < 8; k++) {
            float ar[8];
            *(float4*)&ar[0] = *(const float4*)&As[s][k][ty * 4];
            *(float4*)&ar[4] = *(const float4*)&As[s][k][ty * 4 + 64];
            // B column pairs: adjacent floats reinterpret as f32x2 lanes (16B-aligned)
            unsigned long long b2[4];
            {
                ulonglong2 q0 = *(const ulonglong2*)&Bs[s][k][tx * 4];        // cols tx*4+(0,1),(2,3)
                ulonglong2 q1 = *(const ulonglong2*)&Bs[s][k][tx * 4 + 64];   // cols +64
                b2[0] = q0.x; b2[1] = q0.y; b2[2] = q1.x; b2[3] = q1.y;
            }
#pragma unroll
            for (int i = 0; i < 8; i++) {
                unsigned long long a2;
                PACK_DUP(a2, ar[i]);
                FMA2(acc2[i][0], a2, b2[0]);
                FMA2(acc2[i][1], a2, b2[1]);
                FMA2(acc2[i][2], a2, b2[2]);
                FMA2(acc2[i][3], a2, b2[3]);
            }
        }

        if (bk + 1 < NB) {
            __syncthreads();
            const int ns = s ^ 1;
            As[ns][aCol + 0][aRow] = ta.x;
            As[ns][aCol + 1][aRow] = ta.y;
            As[ns][aCol + 2][aRow] = ta.z;
            As[ns][aCol + 3][aRow] = ta.w;
            *(float4*)&Bs[ns][bRow][bCol] = tb;
            __syncthreads();
        }
    }

    // unpack: accf[i][jh*4+j], cols tx*4 + jh*64 + j  (same layout as proven core)
    float accf[8][8];
#pragma unroll
    for (int i = 0; i < 8; i++)
#pragma unroll
        for (int p = 0; p < 4; p++) {
            uint32_t lo, hi;
            UNPK(lo, hi, acc2[i][p]);
            accf[i][2 * p]     = __uint_as_float(lo);
            accf[i][2 * p + 1] = __uint_as_float(hi);
        }

    // ---------------- epilogue ----------------
    float bf[2][4];
    if (EPI != 3) {
#pragma unroll
        for (int jh = 0; jh < 2; jh++)
            *(float4*)&bf[jh][0] = *(const float4*)(bias + blockN + tx * 4 + jh * 64);
    }
#pragma unroll
    for (int i = 0; i < 8; i++) {
        int row = blockM + ty * 4 + (i & 3) + (i >> 2) * 64;
#pragma unroll
        for (int jh = 0; jh < 2; jh++) {
            int col = blockN + tx * 4 + jh * 64;
            float v[4];
#pragma unroll
            for (int j = 0; j < 4; j++) {
                v[j] = accf[i][jh * 4 + j];
                if (EPI != 3) v[j] += bf[jh][j];
                if (EPI == 1) v[j] = gelu_tanh(v[j]);
            }
            if (EPI == 2) {
                float4 rv = *(const float4*)(resid + (size_t)row * Cstride + col);
                v[0] += rv.x; v[1] += rv.y; v[2] += rv.z; v[3] += rv.w;
            }
            if (EPI == 3) {
#pragma unroll
                for (int j = 0; j < 4; j++)
                    if (col + j < Cstride) C[(size_t)row * Cstride + col + j] = v[j];
            } else {
                *(float4*)(C + (size_t)row * Cstride + col) = make_float4(v[0], v[1], v[2], v[3]);
            }
        }
    }
}

// ---------------- flash-style attention (unchanged from R15) ----------------
#define AQ 64
#define AK 64
#define APITCH 68
#define QS_OFF 0
#define KS_OFF (64*APITCH)
#define VS_OFF (2*64*APITCH)
#define PS_OFF (3*64*APITCH)
#define ATT_SMEM (4*64*APITCH*4)

__global__ void __launch_bounds__(256, 1)
attn_kernel(const float* __restrict__ qkv, float* __restrict__ o)
{
    extern __shared__ float sm[];
    const int tid = threadIdx.x;
    const int tx = tid & 15, ty = tid >> 4;
    const int q0 = blockIdx.x * AQ;
    const int h  = blockIdx.y;
    const int b  = blockIdx.z;

    const size_t rowstride = 3 * DMODEL;
    const float* Qg = qkv + (size_t)(b * SEQ) * rowstride + h * HDIM;
    const float* Kg = Qg + DMODEL;
    const float* Vg = Qg + 2 * DMODEL;

#pragma unroll
    for (int it = 0; it < 4; it++) {
        int i = tid + it * 256;
        int q = i >> 4, d = (i & 15) * 4;
        float4 v = *(const float4*)(Qg + (size_t)(q0 + q) * rowstride + d);
        sm[QS_OFF + (d + 0) * APITCH + q] = v.x * 0.125f;
        sm[QS_OFF + (d + 1) * APITCH + q] = v.y * 0.125f;
        sm[QS_OFF + (d + 2) * APITCH + q] = v.z * 0.125f;
        sm[QS_OFF + (d + 3) * APITCH + q] = v.w * 0.125f;
    }

    float acc_o[4][4];
    float mrow[4], lrow[4];
#pragma unroll
    for (int i = 0; i < 4; i++) {
        mrow[i] = -1e30f; lrow[i] = 0.f;
#pragma unroll
        for (int j = 0; j < 4; j++) acc_o[i][j] = 0.f;
    }

    for (int kt = 0; kt < SEQ / AK; kt++) {
        __syncthreads();
#pragma unroll
        for (int it = 0; it < 4; it++) {
            int i = tid + it * 256;
            int k = i >> 4, d = (i & 15) * 4;
            const float* kp = Kg + (size_t)(kt * AK + k) * rowstride + d;
            float4 kv = *(const float4*)(kp);
            sm[KS_OFF + (d + 0) * APITCH + k] = kv.x;
            sm[KS_OFF + (d + 1) * APITCH + k] = kv.y;
            sm[KS_OFF + (d + 2) * APITCH + k] = kv.z;
            sm[KS_OFF + (d + 3) * APITCH + k] = kv.w;
            float4 vv = *(const float4*)(Vg + (size_t)(kt * AK + k) * rowstride + d);
            *(float4*)&sm[VS_OFF + k * APITCH + d] = vv;
        }
        __syncthreads();

        float s4[4][4];
#pragma unroll
        for (int i = 0; i < 4; i++)
#pragma unroll
            for (int j = 0; j < 4; j++) s4[i][j] = 0.f;
#pragma unroll
        for (int d = 0; d < HDIM; d++) {
            float qr[4], kr[4];
            *(float4*)qr = *(const float4*)&sm[QS_OFF + d * APITCH + ty * 4];
            *(float4*)kr = *(const float4*)&sm[KS_OFF + d * APITCH + tx * 4];
#pragma unroll
            for (int i = 0; i < 4; i++)
#pragma unroll
                for (int j = 0; j < 4; j++)
                    s4[i][j] = fmaf(qr[i], kr[j], s4[i][j]);
        }

#pragma unroll
        for (int i = 0; i < 4; i++) {
            float tm = fmaxf(fmaxf(s4[i][0], s4[i][1]), fmaxf(s4[i][2], s4[i][3]));
#pragma unroll
            for (int off = 8; off > 0; off >>= 1)
                tm = fmaxf(tm, __shfl_xor_sync(0xFFFFFFFFu, tm, off, 16));
            float nm = fmaxf(mrow[i], tm);
            float corr = __expf(mrow[i] - nm);
            mrow[i] = nm;
            float rs = 0.f;
#pragma unroll
            for (int j = 0; j < 4; j++) {
                s4[i][j] = __expf(s4[i][j] - nm);
                rs += s4[i][j];
            }
#pragma unroll
            for (int off = 8; off > 0; off >>= 1)
                rs += __shfl_xor_sync(0xFFFFFFFFu, rs, off, 16);
            lrow[i] = lrow[i] * corr + rs;
#pragma unroll
            for (int j = 0; j < 4; j++) acc_o[i][j] *= corr;
        }

#pragma unroll
        for (int j = 0; j < 4; j++) {
            float4 pv = make_float4(s4[0][j], s4[1][j], s4[2][j], s4[3][j]);
            *(float4*)&sm[PS_OFF + (tx * 4 + j) * APITCH + ty * 4] = pv;
        }
        __syncthreads();

#pragma unroll 4
        for (int k = 0; k < AK; k++) {
            float vr[4];
            *(float4*)vr = *(const float4*)&sm[VS_OFF + k * APITCH + tx * 4];
            float pq[4];
            pq[0] = sm[PS_OFF + k * APITCH + ty * 4 + 0];
            pq[1] = sm[PS_OFF + k * APITCH + ty * 4 + 1];
            pq[2] = sm[PS_OFF + k * APITCH + ty * 4 + 2];
            pq[3] = sm[PS_OFF + k * APITCH + ty * 4 + 3];
#pragma unroll
            for (int i = 0; i < 4; i++)
#pragma unroll
                for (int j = 0; j < 4; j++)
                    acc_o[i][j] = fmaf(pq[i], vr[j], acc_o[i][j]);
        }
    }

#pragma unroll
    for (int i = 0; i < 4; i++) {
        float inv = 1.0f / lrow[i];
        int row = b * SEQ + q0 + ty * 4 + i;
        float4 ov = make_float4(acc_o[i][0] * inv, acc_o[i][1] * inv,
                                acc_o[i][2] * inv, acc_o[i][3] * inv);
        *(float4*)(o + (size_t)row * DMODEL + h * HDIM + tx * 4) = ov;
    }
}

// ---------------- lm_head weight pad ----------------
__global__ void pad_kernel(const float* __restrict__ W, float* __restrict__ P) {
    int idx = blockIdx.x * 256 + threadIdx.x;
    if (idx >= DMODEL * VPAD) return;
    int k = idx / VPAD, n = idx - k * VPAD;
    P[idx] = (n < VOCAB) ? W[(size_t)k * VOCAB + n] : 0.f;
}

// ---------------- embedding ----------------
__global__ void embed_tok_kernel(const int* __restrict__ tok,
                                 const float* __restrict__ te,
                                 float* __restrict__ x) {
    int idx = blockIdx.x * blockDim.x + threadIdx.x;
    if (idx >= ROWS * DMODEL) return;
    int row = idx / DMODEL, d = idx % DMODEL;
    x[idx] = te[(size_t)tok[row] * DMODEL + d];
}
__global__ void embed_pos_kernel(const float* __restrict__ pe, float* __restrict__ x) {
    int idx = blockIdx.x * blockDim.x + threadIdx.x;
    if (idx >= ROWS * DMODEL) return;
    int row = idx / DMODEL, d = idx % DMODEL, s = row % SEQ;
    x[idx] += pe[(size_t)s * DMODEL + d];
}

// ---------------- layernorm ----------------
__global__ void ln_kernel(const float* __restrict__ x,
                          const float* __restrict__ g, const float* __restrict__ b,
                          float* __restrict__ y) {
    int row = blockIdx.x;
    const float* xr = x + (size_t)row * DMODEL;
    __shared__ float red[256];
    int tid = threadIdx.x;

    float s = 0.f;
    for (int i = tid; i < DMODEL; i += 256) s += xr[i];
    red[tid] = s; __syncthreads();
    for (int k = 128; k > 0; k >>= 1) { if (tid < k) red[tid] += red[tid + k]; __syncthreads(); }
    float mean = red[0] * (1.0f / DMODEL);
    __syncthreads();

    float v = 0.f;
    for (int i = tid; i < DMODEL; i += 256) { float d = xr[i] - mean; v += d * d; }
    red[tid] = v; __syncthreads();
    for (int k = 128; k > 0; k >>= 1) { if (tid < k) red[tid] += red[tid + k]; __syncthreads(); }
    float rstd = rsqrtf(red[0] * (1.0f / DMODEL) + 1e-5f);

    float* yr = y + (size_t)row * DMODEL;
    for (int i = tid; i < DMODEL; i += 256)
        yr[i] = (xr[i] - mean) * rstd * g[i] + b[i];
}

// ---------------- launch ----------------
extern "C" void kernel_launch(void* const* d_in, const int* in_sizes, int n_in,
                              void* d_out, int out_size) {
    const int*   tokens    = (const int*)  d_in[0];
    const float* tok_embed = (const float*)d_in[1];
    const float* pos_embed = (const float*)d_in[2];
    const float* ln1_g = (const float*)d_in[3];
    const float* ln1_b = (const float*)d_in[4];
    const float* qkv_w = (const float*)d_in[5];
    const float* qkv_b = (const float*)d_in[6];
    const float* proj_w = (const float*)d_in[7];
    const float* proj_b = (const float*)d_in[8];
    const float* ln2_g = (const float*)d_in[9];
    const float* ln2_b = (const float*)d_in[10];
    const float* ff1_w = (const float*)d_in[11];
    const float* ff1_b = (const float*)d_in[12];
    const float* ff2_w = (const float*)d_in[13];
    const float* ff2_b = (const float*)d_in[14];
    const float* lm_w  = (const float*)d_in[15];
    float* out = (float*)d_out;

    float *px, *ph, *pqkv, *po, *pff, *pwlm;
    cudaGetSymbolAddress((void**)&px,   g_x);
    cudaGetSymbolAddress((void**)&ph,   g_h);
    cudaGetSymbolAddress((void**)&pqkv, g_qkv);
    cudaGetSymbolAddress((void**)&po,   g_o);
    cudaGetSymbolAddress((void**)&pff,  g_ff);
    cudaGetSymbolAddress((void**)&pwlm, g_wlm);

    cudaFuncSetAttribute(attn_kernel, cudaFuncAttributeMaxDynamicSharedMemorySize, ATT_SMEM);

    const int EB = (ROWS * DMODEL + 255) / 256;

    for (int l = 0; l < NLAYER; l++) {
        const float* qw = qkv_w + (size_t)l * DMODEL * 3 * DMODEL;
        const float* qb = qkv_b + (size_t)l * 3 * DMODEL;
        const float* pw = proj_w + (size_t)l * DMODEL * DMODEL;
        const float* pb = proj_b + (size_t)l * DMODEL;
        const float* w1 = ff1_w + (size_t)l * DMODEL * FFDIM;
        const float* b1 = ff1_b + (size_t)l * FFDIM;
        const float* w2 = ff2_w + (size_t)l * FFDIM * DMODEL;
        const float* b2 = ff2_b + (size_t)l * DMODEL;

        if (l == 0) {
            embed_tok_kernel<<<EB, 256>>>(tokens, tok_embed, px);
            embed_pos_kernel<<<EB, 256>>>(pos_embed, px);
        }
        ln_kernel<<<ROWS, 256>>>(px, ln1_g + l * DMODEL, ln1_b + l * DMODEL, ph);
        sgemm<0><<<dim3(3 * DMODEL / 128, ROWS / 128), 256>>>(
            ph, qw, qb, nullptr, pqkv, DMODEL, 3 * DMODEL, 3 * DMODEL);
        attn_kernel<<<dim3(SEQ / AQ, NHEAD, BATCH), 256, ATT_SMEM>>>(pqkv, po);
        sgemm<2><<<dim3(DMODEL / 128, ROWS / 128), 256>>>(
            po, pw, pb, px, px, DMODEL, DMODEL, DMODEL);
        ln_kernel<<<ROWS, 256>>>(px, ln2_g + l * DMODEL, ln2_b + l * DMODEL, ph);
        sgemm<1><<<dim3(FFDIM / 128, ROWS / 128), 256>>>(
            ph, w1, b1, nullptr, pff, DMODEL, FFDIM, FFDIM);
        sgemm<2><<<dim3(DMODEL / 128, ROWS / 128), 256>>>(
            pff, w2, b2, px, px, FFDIM, DMODEL, DMODEL);

        if (l == 0) {
            pad_kernel<<<(DMODEL * VPAD + 255) / 256, 256>>>(lm_w, pwlm);
        }
    }

    // logits = x @ lm_head_w   [2048 x 50257], B padded to stride VPAD
    sgemm<3><<<dim3(VPAD / 128, ROWS / 128), 256>>>(
        px, pwlm, nullptr, nullptr, out, DMODEL, VPAD, VOCAB);
}